// round 7
// baseline (speedup 1.0000x reference)
#include <cuda_runtime.h>
#include <cuda_bf16.h>
#include <cstdint>

// ---------------- problem constants ----------------
#define B_      4
#define CIN     256
#define COUT    128
#define HLO     64
#define WLO     64
#define PLO     (HLO*WLO)      // 4096 low-res pixels
#define CRED    32
#define GROUPS  8
#define GC_     16
#define KK      25             // 5x5
#define SPAN    (KK*GROUPS)    // 200
#define HF      128
#define WF      128

// ---------------- scratch ----------------
__device__ float g_h0 [B_ * COUT * PLO];   // 8.4 MB
__device__ float g_wgt[B_ * SPAN * PLO];   // 13.1 MB

// ---------------- packed f32x2 helpers ----------------
__device__ __forceinline__ unsigned long long fma2(unsigned long long a,
                                                   unsigned long long b,
                                                   unsigned long long c) {
    unsigned long long d;
    asm("fma.rn.f32x2 %0, %1, %2, %3;" : "=l"(d) : "l"(a), "l"(b), "l"(c));
    return d;
}
__device__ __forceinline__ unsigned long long pack2(float v) {
    unsigned long long d;
    asm("mov.b64 %0, {%1, %1};" : "=l"(d) : "f"(v), "f"(v));
    return d;
}
__device__ __forceinline__ unsigned long long packab(float a, float b) {
    unsigned long long d;
    asm("mov.b64 %0, {%1, %2};" : "=l"(d) : "f"(a), "f"(b));
    return d;
}
union F2U { unsigned long long u; float2 f; };

// =====================================================================
// K1: h0 = W1x1 @ X  per batch  [128 x 256] x [256 x 4096]
// 512 threads, tile 128co x 128px, per-thread 4co x 8px.
// W stored duplicated (u64) in smem -> no pack MOVs in inner loop.
// =====================================================================
__global__ __launch_bounds__(512, 1)
void k1_conv1x1(const float* __restrict__ x,
                const float* __restrict__ w,
                const float* __restrict__ bias) {
    __shared__ float Xs[8][128];
    __shared__ unsigned long long Ws2[8][128];

    const int bb = blockIdx.y;
    const int p0 = blockIdx.x * 128;
    const int t  = threadIdx.x;
    const int ty = t >> 4;     // 0..31 (co group)
    const int tx = t & 15;     // 0..15 (px group)

    unsigned long long acc[4][4];
#pragma unroll
    for (int i = 0; i < 4; i++)
#pragma unroll
        for (int j = 0; j < 4; j++) acc[i][j] = 0ull;

    const float* xb = x + (size_t)bb * CIN * PLO + p0;

    for (int k0 = 0; k0 < CIN; k0 += 8) {
        if (t < 256) {               // X tile: 8 k-rows x 128 px
            int kk = t >> 5;
            int c4 = (t & 31) * 4;
            float4 v = *(const float4*)(xb + (size_t)(k0 + kk) * PLO + c4);
            *(float4*)&Xs[kk][c4] = v;
        } else {                     // W tile, duplicated halves
            int u   = t - 256;
            int co  = u >> 1;
            int kk4 = (u & 1) * 4;
            float4 v = *(const float4*)(w + co * CIN + k0 + kk4);
            Ws2[kk4 + 0][co] = pack2(v.x);
            Ws2[kk4 + 1][co] = pack2(v.y);
            Ws2[kk4 + 2][co] = pack2(v.z);
            Ws2[kk4 + 3][co] = pack2(v.w);
        }
        __syncthreads();
#pragma unroll
        for (int kk = 0; kk < 8; kk++) {
            unsigned long long wp[4], xr[4];
#pragma unroll
            for (int i = 0; i < 4; i++) wp[i] = Ws2[kk][ty + 32 * i];
#pragma unroll
            for (int j = 0; j < 4; j++)
                xr[j] = *(const unsigned long long*)&Xs[kk][2 * tx + 32 * j];
#pragma unroll
            for (int i = 0; i < 4; i++)
#pragma unroll
                for (int j = 0; j < 4; j++)
                    acc[i][j] = fma2(wp[i], xr[j], acc[i][j]);
        }
        __syncthreads();
    }

#pragma unroll
    for (int i = 0; i < 4; i++) {
        int co = ty + 32 * i;
        float bv = bias[co];
        float* op = g_h0 + ((size_t)bb * COUT + co) * PLO + p0;
#pragma unroll
        for (int j = 0; j < 4; j++) {
            F2U v; v.u = acc[i][j];
            *(float2*)&op[2 * tx + 32 * j] = make_float2(v.f.x + bv, v.f.y + bv);
        }
    }
}

// =====================================================================
// K2: kernel-gen at 64x64. 512 threads, 128-px tile.
//   stage A: r = relu(BN(w_red @ h0)) ; per-thread 1cr x 8px
//   stage B: wgt = w_span @ r ; 400 threads, 2 per cout (64px halves)
// =====================================================================
__global__ __launch_bounds__(512, 1)
void k2_kernelgen(const float* __restrict__ w_red,  const float* __restrict__ b_red,
                  const float* __restrict__ gamma,  const float* __restrict__ beta,
                  const float* __restrict__ mean,   const float* __restrict__ var,
                  const float* __restrict__ w_span, const float* __restrict__ b_span) {
    __shared__ float Hs[32][128];
    __shared__ unsigned long long Wr2[32][32];
    __shared__ float Rs[32][132];

    const int bb = blockIdx.y;
    const int p0 = blockIdx.x * 128;
    const int t  = threadIdx.x;
    const int ty = t >> 4;   // 0..31 == cr
    const int tx = t & 15;

    unsigned long long acc[4];
#pragma unroll
    for (int j = 0; j < 4; j++) acc[j] = 0ull;

    for (int k0 = 0; k0 < COUT; k0 += 32) {
#pragma unroll
        for (int q = 0; q < 2; q++) {       // H tile: 32 rows x 128 px
            int f   = t + 512 * q;
            int row = f >> 5;
            int c4  = (f & 31) * 4;
            float4 v = *(const float4*)(g_h0 + ((size_t)(bb * COUT + k0 + row)) * PLO + p0 + c4);
            *(float4*)&Hs[row][c4] = v;
        }
        if (t < 256) {                      // W_red tile, duplicated
            int cr  = t >> 3;
            int kk4 = (t & 7) * 4;
            float4 v = *(const float4*)(w_red + cr * COUT + k0 + kk4);
            Wr2[kk4 + 0][cr] = pack2(v.x);
            Wr2[kk4 + 1][cr] = pack2(v.y);
            Wr2[kk4 + 2][cr] = pack2(v.z);
            Wr2[kk4 + 3][cr] = pack2(v.w);
        }
        __syncthreads();
#pragma unroll
        for (int kk = 0; kk < 32; kk++) {
            unsigned long long wp = Wr2[kk][ty];
#pragma unroll
            for (int j = 0; j < 4; j++) {
                unsigned long long xv = *(const unsigned long long*)&Hs[kk][2 * tx + 32 * j];
                acc[j] = fma2(wp, xv, acc[j]);
            }
        }
        __syncthreads();
    }

    // BN + ReLU -> Rs
    {
        int cr = ty;
        float sc  = gamma[cr] * rsqrtf(var[cr] + 1e-5f);
        float off = (b_red[cr] - mean[cr]) * sc + beta[cr];
#pragma unroll
        for (int j = 0; j < 4; j++) {
            F2U v; v.u = acc[j];
            Rs[cr][2 * tx + 32 * j]     = fmaxf(v.f.x * sc + off, 0.f);
            Rs[cr][2 * tx + 32 * j + 1] = fmaxf(v.f.y * sc + off, 0.f);
        }
    }
    __syncthreads();

    // stage B
    if (t < 2 * SPAN) {
        const int co = t >> 1;
        const int pb = (t & 1) * 64;
        unsigned long long wp[CRED];
        const float* wsp = w_span + co * CRED;
#pragma unroll
        for (int k = 0; k < CRED; k++) wp[k] = pack2(__ldg(wsp + k));
        const float bs = b_span[co];
        float* wout = g_wgt + ((size_t)bb * SPAN + co) * PLO + p0 + pb;

        for (int p4 = 0; p4 < 64; p4 += 4) {
            unsigned long long a0 = pack2(bs), a1 = pack2(bs);
#pragma unroll
            for (int k = 0; k < CRED; k++) {
                ulonglong2 rv = *(const ulonglong2*)&Rs[k][pb + p4];
                a0 = fma2(wp[k], rv.x, a0);
                a1 = fma2(wp[k], rv.y, a1);
            }
            F2U u0, u1; u0.u = a0; u1.u = a1;
            *(float4*)&wout[p4] = make_float4(u0.f.x, u0.f.y, u1.f.x, u1.f.y);
        }
    }
}

// =====================================================================
// K3: involution, fully f32x2-packed 2x2 outputs.
//  column pairs (c0,c1) per kw: (0,0),(0,1),(1,1),(1,2),(2,2)
//  row pairs    (r0,r1) per kh: same table.
// Weights stored duplicated (u64) in dynamic smem.
// =====================================================================
__global__ __launch_bounds__(256)
void k3_involution(float* __restrict__ outp) {
    extern __shared__ unsigned long long smemRaw[];
    unsigned long long* Wg2 = smemRaw;                    // [25][256] u64
    float* Hs = (float*)(smemRaw + KK * 256);             // [16][336]

    const int tile = blockIdx.x;
    const int g    = blockIdx.y;
    const int bb   = blockIdx.z;
    const int m0   = (tile >> 2) * 16;
    const int n0   = (tile & 3) * 16;
    const int t    = threadIdx.x;

    // h0 slice with zero halo
    for (int idx = t; idx < 16 * 324; idx += 256) {
        int c  = idx / 324;
        int r2 = idx - c * 324;
        int mm = r2 / 18;
        int nn = r2 - mm * 18;
        int gm = m0 + mm - 1;
        int gn = n0 + nn - 1;
        float v = 0.f;
        if (gm >= 0 && gm < HLO && gn >= 0 && gn < WLO)
            v = g_h0[((size_t)(bb * COUT + g * GC_ + c)) * PLO + gm * WLO + gn];
        Hs[c * 336 + mm * 18 + nn] = v;
    }
    // weights, duplicated
    for (int idx = t; idx < KK * 256; idx += 256) {
        int k  = idx >> 8;
        int pp = idx & 255;
        int ml = pp >> 4;
        int nl = pp & 15;
        Wg2[idx] = pack2(g_wgt[((size_t)(bb * SPAN + g * KK + k)) * PLO
                               + (m0 + ml) * WLO + (n0 + nl)]);
    }
    __syncthreads();

    const int c  = t >> 4;
    const int nl = t & 15;
    const int xg = (n0 + nl) * 2;
    const float* hbase = Hs + c * 336 + nl;

    for (int ml = 0; ml < 16; ml++) {
        unsigned long long w2[KK];
#pragma unroll
        for (int k = 0; k < KK; k++) w2[k] = Wg2[k * 256 + ml * 16 + nl];

        float h[3][3];
#pragma unroll
        for (int dr = 0; dr < 3; dr++)
#pragma unroll
            for (int dc = 0; dc < 3; dc++)
                h[dr][dc] = hbase[(ml + dr) * 18 + dc];

        // column-pair packs per row: (h0,h0),(h0,h1),(h1,h1),(h1,h2),(h2,h2)
        unsigned long long pr[3][5];
#pragma unroll
        for (int r = 0; r < 3; r++) {
            pr[r][0] = pack2 (h[r][0]);
            pr[r][1] = packab(h[r][0], h[r][1]);
            pr[r][2] = pack2 (h[r][1]);
            pr[r][3] = packab(h[r][1], h[r][2]);
            pr[r][4] = pack2 (h[r][2]);
        }

        const int R0[5] = {0, 0, 1, 1, 2};
        const int R1[5] = {0, 1, 1, 2, 2};
        unsigned long long at = 0ull, ab = 0ull;
#pragma unroll
        for (int kh = 0; kh < 5; kh++) {
#pragma unroll
            for (int kw = 0; kw < 5; kw++) {
                unsigned long long wv = w2[kh * 5 + kw];
                at = fma2(wv, pr[R0[kh]][kw], at);
                ab = fma2(wv, pr[R1[kh]][kw], ab);
            }
        }
        const int yb = (m0 + ml) * 2;
        size_t ob = ((size_t)(bb * COUT + g * GC_ + c) * HF + yb) * WF + xg;
        F2U ut, ub; ut.u = at; ub.u = ab;
        *(float2*)&outp[ob]      = ut.f;
        *(float2*)&outp[ob + WF] = ub.f;
    }
}

#define K3_SMEM (KK * 256 * 8 + 16 * 336 * 4)   // 72704 bytes

// =====================================================================
extern "C" void kernel_launch(void* const* d_in, const int* in_sizes, int n_in,
                              void* d_out, int out_size) {
    const float* x      = (const float*)d_in[0];
    const float* w1x1   = (const float*)d_in[1];
    const float* b1x1   = (const float*)d_in[2];
    const float* w_red  = (const float*)d_in[3];
    const float* b_red  = (const float*)d_in[4];
    const float* gamma  = (const float*)d_in[5];
    const float* beta   = (const float*)d_in[6];
    const float* mean   = (const float*)d_in[7];
    const float* var    = (const float*)d_in[8];
    const float* w_span = (const float*)d_in[9];
    const float* b_span = (const float*)d_in[10];
    float* out = (float*)d_out;

    // idempotent, not a stream op (capture-safe); called every time — no
    // static guards allowed by the harness contract.
    cudaFuncSetAttribute(k3_involution,
                         cudaFuncAttributeMaxDynamicSharedMemorySize, K3_SMEM);

    k1_conv1x1 <<<dim3(PLO / 128, B_), 512>>>(x, w1x1, b1x1);
    k2_kernelgen<<<dim3(PLO / 128, B_), 512>>>(w_red, b_red, gamma, beta, mean, var,
                                               w_span, b_span);
    k3_involution<<<dim3(16, GROUPS, B_), 256, K3_SMEM>>>(out);
}

// round 8
// speedup vs baseline: 1.1316x; 1.1316x over previous
#include <cuda_runtime.h>
#include <cuda_bf16.h>
#include <cstdint>

// ---------------- problem constants ----------------
#define B_      4
#define CIN     256
#define COUT    128
#define HLO     64
#define WLO     64
#define PLO     (HLO*WLO)      // 4096
#define CRED    32
#define GROUPS  8
#define GC_     16
#define KK      25
#define SPAN    (KK*GROUPS)    // 200
#define HF      128
#define WF      128

// ---------------- scratch ----------------
__device__ float g_h0 [B_ * COUT * PLO];   // 8.4 MB
__device__ float g_wgt[B_ * SPAN * PLO];   // 13.1 MB

// ---------------- packed f32x2 helpers ----------------
__device__ __forceinline__ unsigned long long fma2(unsigned long long a,
                                                   unsigned long long b,
                                                   unsigned long long c) {
    unsigned long long d;
    asm("fma.rn.f32x2 %0, %1, %2, %3;" : "=l"(d) : "l"(a), "l"(b), "l"(c));
    return d;
}
__device__ __forceinline__ unsigned long long pack2(float v) {
    unsigned long long d;
    asm("mov.b64 %0, {%1, %1};" : "=l"(d) : "f"(v), "f"(v));
    return d;
}
__device__ __forceinline__ unsigned long long packab(float a, float b) {
    unsigned long long d;
    asm("mov.b64 %0, {%1, %2};" : "=l"(d) : "f"(a), "f"(b));
    return d;
}
union F2U { unsigned long long u; float2 f; };

// =====================================================================
// K1: h0 = W1x1 @ X per batch. Tile 128co x 128px, 256 thr, 8co x 8px/thread.
// Register double-buffered: LDG of k-tile (n+1) overlaps compute of tile n.
// =====================================================================
__global__ __launch_bounds__(256)
void k1_conv1x1(const float* __restrict__ x,
                const float* __restrict__ w,
                const float* __restrict__ bias) {
    __shared__ float Xs[8][128];
    __shared__ unsigned long long Ws2[8][128];   // W duplicated as f32x2

    const int bb = blockIdx.y;
    const int p0 = blockIdx.x * 128;
    const int t  = threadIdx.x;
    const int ty = t >> 4;     // 0..15 -> 8 co each (ty + 16*i)
    const int tx = t & 15;     // 0..15 -> 8 px each (2*tx + 32*j)

    unsigned long long acc[8][4];
#pragma unroll
    for (int i = 0; i < 8; i++)
#pragma unroll
        for (int j = 0; j < 4; j++) acc[i][j] = 0ull;

    const float* xb = x + (size_t)bb * CIN * PLO + p0;
    // per-thread load slices
    const int xrow = t >> 5;          // 0..7
    const int xcol = (t & 31) * 4;    // 0..124
    const int wco  = t >> 1;          // 0..127
    const int wk4  = (t & 1) * 4;     // 0 or 4

    // preload k-tile 0 into registers
    float4 xv = *(const float4*)(xb + (size_t)xrow * PLO + xcol);
    float4 wv = *(const float4*)(w + wco * CIN + wk4);

    for (int k0 = 0; k0 < CIN; k0 += 8) {
        // stage current tile to smem
        *(float4*)&Xs[xrow][xcol] = xv;
        Ws2[wk4 + 0][wco] = pack2(wv.x);
        Ws2[wk4 + 1][wco] = pack2(wv.y);
        Ws2[wk4 + 2][wco] = pack2(wv.z);
        Ws2[wk4 + 3][wco] = pack2(wv.w);
        __syncthreads();

        // prefetch next tile (latency overlapped with compute below)
        if (k0 + 8 < CIN) {
            xv = *(const float4*)(xb + (size_t)(k0 + 8 + xrow) * PLO + xcol);
            wv = *(const float4*)(w + wco * CIN + k0 + 8 + wk4);
        }

#pragma unroll
        for (int kk = 0; kk < 8; kk++) {
            unsigned long long wp[8], xr[4];
#pragma unroll
            for (int i = 0; i < 8; i++) wp[i] = Ws2[kk][ty + 16 * i];
#pragma unroll
            for (int j = 0; j < 4; j++)
                xr[j] = *(const unsigned long long*)&Xs[kk][2 * tx + 32 * j];
#pragma unroll
            for (int i = 0; i < 8; i++)
#pragma unroll
                for (int j = 0; j < 4; j++)
                    acc[i][j] = fma2(wp[i], xr[j], acc[i][j]);
        }
        __syncthreads();
    }

#pragma unroll
    for (int i = 0; i < 8; i++) {
        int co = ty + 16 * i;
        float bv = bias[co];
        float* op = g_h0 + ((size_t)bb * COUT + co) * PLO + p0;
#pragma unroll
        for (int j = 0; j < 4; j++) {
            F2U v; v.u = acc[i][j];
            *(float2*)&op[2 * tx + 32 * j] = make_float2(v.f.x + bv, v.f.y + bv);
        }
    }
}

// =====================================================================
// K2: kernel-gen at 64x64, 512 thr, 128-px tile, double-buffered H loads.
// =====================================================================
__global__ __launch_bounds__(512, 1)
void k2_kernelgen(const float* __restrict__ w_red,  const float* __restrict__ b_red,
                  const float* __restrict__ gamma,  const float* __restrict__ beta,
                  const float* __restrict__ mean,   const float* __restrict__ var,
                  const float* __restrict__ w_span, const float* __restrict__ b_span) {
    __shared__ float Hs[32][128];
    __shared__ unsigned long long Wr2[32][32];
    __shared__ float Rs[32][132];

    const int bb = blockIdx.y;
    const int p0 = blockIdx.x * 128;
    const int t  = threadIdx.x;
    const int ty = t >> 4;   // 0..31 == cr
    const int tx = t & 15;

    unsigned long long acc[4];
#pragma unroll
    for (int j = 0; j < 4; j++) acc[j] = 0ull;

    const float* hb = g_h0 + (size_t)bb * COUT * PLO + p0;
    const int hrow0 = t >> 5;            // 0..15
    const int hrow1 = hrow0 + 16;        // 16..31
    const int hcol  = (t & 31) * 4;
    const int wcr   = t >> 3;            // 0..63 (t<256 used)
    const int wk4   = (t & 7) * 4;

    // preload k0 = 0
    float4 hv0 = *(const float4*)(hb + (size_t)hrow0 * PLO + hcol);
    float4 hv1 = *(const float4*)(hb + (size_t)hrow1 * PLO + hcol);
    float4 wv;
    if (t < 256) wv = *(const float4*)(w_red + wcr * COUT + wk4);

    for (int k0 = 0; k0 < COUT; k0 += 32) {
        *(float4*)&Hs[hrow0][hcol] = hv0;
        *(float4*)&Hs[hrow1][hcol] = hv1;
        if (t < 256) {
            Wr2[wk4 + 0][wcr] = pack2(wv.x);
            Wr2[wk4 + 1][wcr] = pack2(wv.y);
            Wr2[wk4 + 2][wcr] = pack2(wv.z);
            Wr2[wk4 + 3][wcr] = pack2(wv.w);
        }
        __syncthreads();

        if (k0 + 32 < COUT) {
            hv0 = *(const float4*)(hb + (size_t)(k0 + 32 + hrow0) * PLO + hcol);
            hv1 = *(const float4*)(hb + (size_t)(k0 + 32 + hrow1) * PLO + hcol);
            if (t < 256) wv = *(const float4*)(w_red + wcr * COUT + k0 + 32 + wk4);
        }

#pragma unroll
        for (int kk = 0; kk < 32; kk++) {
            unsigned long long wp = Wr2[kk][ty];
#pragma unroll
            for (int j = 0; j < 4; j++) {
                unsigned long long xv2 = *(const unsigned long long*)&Hs[kk][2 * tx + 32 * j];
                acc[j] = fma2(wp, xv2, acc[j]);
            }
        }
        __syncthreads();
    }

    {   // BN + ReLU -> Rs
        int cr = ty;
        float sc  = gamma[cr] * rsqrtf(var[cr] + 1e-5f);
        float off = (b_red[cr] - mean[cr]) * sc + beta[cr];
#pragma unroll
        for (int j = 0; j < 4; j++) {
            F2U v; v.u = acc[j];
            Rs[cr][2 * tx + 32 * j]     = fmaxf(v.f.x * sc + off, 0.f);
            Rs[cr][2 * tx + 32 * j + 1] = fmaxf(v.f.y * sc + off, 0.f);
        }
    }
    __syncthreads();

    // stage B: 400 threads, 2 per cout (64-px halves)
    if (t < 2 * SPAN) {
        const int co = t >> 1;
        const int pb = (t & 1) * 64;
        unsigned long long wp[CRED];
        const float* wsp = w_span + co * CRED;
#pragma unroll
        for (int k = 0; k < CRED; k++) wp[k] = pack2(__ldg(wsp + k));
        const float bs = b_span[co];
        float* wout = g_wgt + ((size_t)bb * SPAN + co) * PLO + p0 + pb;

        for (int p4 = 0; p4 < 64; p4 += 4) {
            unsigned long long a0 = pack2(bs), a1 = pack2(bs);
#pragma unroll
            for (int k = 0; k < CRED; k++) {
                ulonglong2 rv = *(const ulonglong2*)&Rs[k][pb + p4];
                a0 = fma2(wp[k], rv.x, a0);
                a1 = fma2(wp[k], rv.y, a1);
            }
            F2U u0, u1; u0.u = a0; u1.u = a1;
            *(float4*)&wout[p4] = make_float4(u0.f.x, u0.f.y, u1.f.x, u1.f.y);
        }
    }
}

// =====================================================================
// K3: involution, f32x2-packed 2x2 outputs (unchanged from R4 candidate).
// =====================================================================
__global__ __launch_bounds__(256)
void k3_involution(float* __restrict__ outp) {
    extern __shared__ unsigned long long smemRaw[];
    unsigned long long* Wg2 = smemRaw;                    // [25][256]
    float* Hs = (float*)(smemRaw + KK * 256);             // [16][336]

    const int tile = blockIdx.x;
    const int g    = blockIdx.y;
    const int bb   = blockIdx.z;
    const int m0   = (tile >> 2) * 16;
    const int n0   = (tile & 3) * 16;
    const int t    = threadIdx.x;

    for (int idx = t; idx < 16 * 324; idx += 256) {
        int c  = idx / 324;
        int r2 = idx - c * 324;
        int mm = r2 / 18;
        int nn = r2 - mm * 18;
        int gm = m0 + mm - 1;
        int gn = n0 + nn - 1;
        float v = 0.f;
        if (gm >= 0 && gm < HLO && gn >= 0 && gn < WLO)
            v = g_h0[((size_t)(bb * COUT + g * GC_ + c)) * PLO + gm * WLO + gn];
        Hs[c * 336 + mm * 18 + nn] = v;
    }
    for (int idx = t; idx < KK * 256; idx += 256) {
        int k  = idx >> 8;
        int pp = idx & 255;
        int ml = pp >> 4;
        int nl = pp & 15;
        Wg2[idx] = pack2(g_wgt[((size_t)(bb * SPAN + g * KK + k)) * PLO
                               + (m0 + ml) * WLO + (n0 + nl)]);
    }
    __syncthreads();

    const int c  = t >> 4;
    const int nl = t & 15;
    const int xg = (n0 + nl) * 2;
    const float* hbase = Hs + c * 336 + nl;

    for (int ml = 0; ml < 16; ml++) {
        unsigned long long w2[KK];
#pragma unroll
        for (int k = 0; k < KK; k++) w2[k] = Wg2[k * 256 + ml * 16 + nl];

        float h[3][3];
#pragma unroll
        for (int dr = 0; dr < 3; dr++)
#pragma unroll
            for (int dc = 0; dc < 3; dc++)
                h[dr][dc] = hbase[(ml + dr) * 18 + dc];

        unsigned long long pr[3][5];
#pragma unroll
        for (int r = 0; r < 3; r++) {
            pr[r][0] = pack2 (h[r][0]);
            pr[r][1] = packab(h[r][0], h[r][1]);
            pr[r][2] = pack2 (h[r][1]);
            pr[r][3] = packab(h[r][1], h[r][2]);
            pr[r][4] = pack2 (h[r][2]);
        }

        const int R0[5] = {0, 0, 1, 1, 2};
        const int R1[5] = {0, 1, 1, 2, 2};
        unsigned long long at = 0ull, ab = 0ull;
#pragma unroll
        for (int kh = 0; kh < 5; kh++) {
#pragma unroll
            for (int kw = 0; kw < 5; kw++) {
                unsigned long long wv = w2[kh * 5 + kw];
                at = fma2(wv, pr[R0[kh]][kw], at);
                ab = fma2(wv, pr[R1[kh]][kw], ab);
            }
        }
        const int yb = (m0 + ml) * 2;
        size_t ob = ((size_t)(bb * COUT + g * GC_ + c) * HF + yb) * WF + xg;
        F2U ut, ub; ut.u = at; ub.u = ab;
        *(float2*)&outp[ob]      = ut.f;
        *(float2*)&outp[ob + WF] = ub.f;
    }
}

#define K3_SMEM (KK * 256 * 8 + 16 * 336 * 4)   // 72704 bytes

// =====================================================================
extern "C" void kernel_launch(void* const* d_in, const int* in_sizes, int n_in,
                              void* d_out, int out_size) {
    const float* x      = (const float*)d_in[0];
    const float* w1x1   = (const float*)d_in[1];
    const float* b1x1   = (const float*)d_in[2];
    const float* w_red  = (const float*)d_in[3];
    const float* b_red  = (const float*)d_in[4];
    const float* gamma  = (const float*)d_in[5];
    const float* beta   = (const float*)d_in[6];
    const float* mean   = (const float*)d_in[7];
    const float* var    = (const float*)d_in[8];
    const float* w_span = (const float*)d_in[9];
    const float* b_span = (const float*)d_in[10];
    float* out = (float*)d_out;

    cudaFuncSetAttribute(k3_involution,
                         cudaFuncAttributeMaxDynamicSharedMemorySize, K3_SMEM);

    k1_conv1x1 <<<dim3(PLO / 128, B_), 256>>>(x, w1x1, b1x1);
    k2_kernelgen<<<dim3(PLO / 128, B_), 512>>>(w_red, b_red, gamma, beta, mean, var,
                                               w_span, b_span);
    k3_involution<<<dim3(16, GROUPS, B_), 256, K3_SMEM>>>(out);
}

// round 9
// speedup vs baseline: 1.3846x; 1.2236x over previous
#include <cuda_runtime.h>
#include <cuda_bf16.h>
#include <cstdint>

// ---------------- problem constants ----------------
#define B_      4
#define CIN     256
#define COUT    128
#define HLO     64
#define WLO     64
#define PLO     (HLO*WLO)      // 4096
#define CRED    32
#define GROUPS  8
#define GC_     16
#define KK      25
#define SPAN    (KK*GROUPS)    // 200
#define HF      128
#define WF      128

// ---------------- scratch ----------------
__device__ float g_h0 [B_ * COUT * PLO];   // 8.4 MB
__device__ float g_wgt[B_ * SPAN * PLO];   // 13.1 MB

// ---------------- packed f32x2 helpers ----------------
__device__ __forceinline__ unsigned long long fma2(unsigned long long a,
                                                   unsigned long long b,
                                                   unsigned long long c) {
    unsigned long long d;
    asm("fma.rn.f32x2 %0, %1, %2, %3;" : "=l"(d) : "l"(a), "l"(b), "l"(c));
    return d;
}
__device__ __forceinline__ unsigned long long pack2(float v) {
    unsigned long long d;
    asm("mov.b64 %0, {%1, %1};" : "=l"(d) : "f"(v), "f"(v));
    return d;
}
union F2U { unsigned long long u; float2 f; };

// =====================================================================
// K1: h0 = W1x1 @ X per batch.
// 128-thread CTAs, tile 64co x 128px, per-thread 8co x 8px (same
// LDS/FFMA2 ratio as before). Grid 256 CTAs -> 4 CTAs/SM resident
// (launch_bounds 128,4), all 148 SMs covered. Register double-buffered.
// =====================================================================
__global__ __launch_bounds__(128, 4)
void k1_conv1x1(const float* __restrict__ x,
                const float* __restrict__ w,
                const float* __restrict__ bias) {
    __shared__ float Xs[8][128];
    __shared__ unsigned long long Ws2[8][64];   // 64 co, duplicated f32x2

    const int bb = blockIdx.z;
    const int ch = blockIdx.y;          // co half: 0 or 1 (64 co each)
    const int p0 = blockIdx.x * 128;
    const int t  = threadIdx.x;
    const int ty = t >> 4;              // 0..7  -> 8 co each (ty + 8*i)
    const int tx = t & 15;              // 0..15 -> 8 px each (2*tx + 32*j)

    unsigned long long acc[8][4];
#pragma unroll
    for (int i = 0; i < 8; i++)
#pragma unroll
        for (int j = 0; j < 4; j++) acc[i][j] = 0ull;

    const float* xb = x + (size_t)bb * CIN * PLO + p0;
    const float* wb = w + (size_t)(ch * 64) * CIN;

    // load slices: X = 2 float4/thread, W = 1 float4/thread
    const int xr0  = t >> 5;            // rows 0..3
    const int xr1  = xr0 + 4;           // rows 4..7
    const int xcol = (t & 31) * 4;
    const int wco  = t >> 1;            // 0..63
    const int wk4  = (t & 1) * 4;       // 0 or 4

    float4 xv0 = *(const float4*)(xb + (size_t)xr0 * PLO + xcol);
    float4 xv1 = *(const float4*)(xb + (size_t)xr1 * PLO + xcol);
    float4 wv  = *(const float4*)(wb + wco * CIN + wk4);

    for (int k0 = 0; k0 < CIN; k0 += 8) {
        *(float4*)&Xs[xr0][xcol] = xv0;
        *(float4*)&Xs[xr1][xcol] = xv1;
        Ws2[wk4 + 0][wco] = pack2(wv.x);
        Ws2[wk4 + 1][wco] = pack2(wv.y);
        Ws2[wk4 + 2][wco] = pack2(wv.z);
        Ws2[wk4 + 3][wco] = pack2(wv.w);
        __syncthreads();

        if (k0 + 8 < CIN) {             // prefetch next k-tile
            xv0 = *(const float4*)(xb + (size_t)(k0 + 8 + xr0) * PLO + xcol);
            xv1 = *(const float4*)(xb + (size_t)(k0 + 8 + xr1) * PLO + xcol);
            wv  = *(const float4*)(wb + wco * CIN + k0 + 8 + wk4);
        }

#pragma unroll
        for (int kk = 0; kk < 8; kk++) {
            unsigned long long wp[8], xr[4];
#pragma unroll
            for (int i = 0; i < 8; i++) wp[i] = Ws2[kk][ty + 8 * i];
#pragma unroll
            for (int j = 0; j < 4; j++)
                xr[j] = *(const unsigned long long*)&Xs[kk][2 * tx + 32 * j];
#pragma unroll
            for (int i = 0; i < 8; i++)
#pragma unroll
                for (int j = 0; j < 4; j++)
                    acc[i][j] = fma2(wp[i], xr[j], acc[i][j]);
        }
        __syncthreads();
    }

#pragma unroll
    for (int i = 0; i < 8; i++) {
        int co = ch * 64 + ty + 8 * i;
        float bv = bias[co];
        float* op = g_h0 + ((size_t)bb * COUT + co) * PLO + p0;
#pragma unroll
        for (int j = 0; j < 4; j++) {
            F2U v; v.u = acc[i][j];
            *(float2*)&op[2 * tx + 32 * j] = make_float2(v.f.x + bv, v.f.y + bv);
        }
    }
}

// =====================================================================
// K2: kernel-gen at 64x64 (R3-measured version, 256 threads).
// =====================================================================
__global__ __launch_bounds__(256, 1)
void k2_kernelgen(const float* __restrict__ w_red,  const float* __restrict__ b_red,
                  const float* __restrict__ gamma,  const float* __restrict__ beta,
                  const float* __restrict__ mean,   const float* __restrict__ var,
                  const float* __restrict__ w_span, const float* __restrict__ b_span) {
    __shared__ float Hs[32][128];
    __shared__ float Wrs[32][33];
    __shared__ float Rs[32][132];

    const int bb = blockIdx.y;
    const int p0 = blockIdx.x * 128;
    const int t  = threadIdx.x;
    const int ty = t >> 4;
    const int tx = t & 15;

    unsigned long long acc[2][4];
#pragma unroll
    for (int i = 0; i < 2; i++)
#pragma unroll
        for (int j = 0; j < 4; j++) acc[i][j] = 0ull;

    for (int k0 = 0; k0 < COUT; k0 += 32) {
#pragma unroll
        for (int q = 0; q < 4; q++) {
            int f   = t + 256 * q;
            int row = f >> 5;
            int c4  = (f & 31) * 4;
            float4 v = *(const float4*)(g_h0 + ((size_t)(bb * COUT + k0 + row)) * PLO + p0 + c4);
            *(float4*)&Hs[row][c4] = v;
        }
        {
            int cr  = t >> 3;
            int kk4 = (t & 7) * 4;
            float4 v = *(const float4*)(w_red + cr * COUT + k0 + kk4);
            Wrs[kk4 + 0][cr] = v.x; Wrs[kk4 + 1][cr] = v.y;
            Wrs[kk4 + 2][cr] = v.z; Wrs[kk4 + 3][cr] = v.w;
        }
        __syncthreads();
#pragma unroll
        for (int kk = 0; kk < 32; kk++) {
            unsigned long long wp0 = pack2(Wrs[kk][ty]);
            unsigned long long wp1 = pack2(Wrs[kk][ty + 16]);
#pragma unroll
            for (int j = 0; j < 4; j++) {
                unsigned long long xv = *(const unsigned long long*)&Hs[kk][2 * tx + 32 * j];
                acc[0][j] = fma2(wp0, xv, acc[0][j]);
                acc[1][j] = fma2(wp1, xv, acc[1][j]);
            }
        }
        __syncthreads();
    }

#pragma unroll
    for (int i = 0; i < 2; i++) {
        int cr = ty + 16 * i;
        float sc  = gamma[cr] * rsqrtf(var[cr] + 1e-5f);
        float off = (b_red[cr] - mean[cr]) * sc + beta[cr];
#pragma unroll
        for (int j = 0; j < 4; j++) {
            F2U v; v.u = acc[i][j];
            Rs[cr][2 * tx + 32 * j]     = fmaxf(v.f.x * sc + off, 0.f);
            Rs[cr][2 * tx + 32 * j + 1] = fmaxf(v.f.y * sc + off, 0.f);
        }
    }
    __syncthreads();

    if (t < SPAN) {
        const int co = t;
        unsigned long long wp[CRED];
        const float* wsp = w_span + co * CRED;
#pragma unroll
        for (int k = 0; k < CRED; k++) wp[k] = pack2(__ldg(wsp + k));
        const float bs = b_span[co];
        float* wout = g_wgt + ((size_t)bb * SPAN + co) * PLO + p0;

        for (int p4 = 0; p4 < 128; p4 += 4) {
            unsigned long long a0 = pack2(bs), a1 = pack2(bs);
#pragma unroll
            for (int k = 0; k < CRED; k++) {
                ulonglong2 rv = *(const ulonglong2*)&Rs[k][p4];
                a0 = fma2(wp[k], rv.x, a0);
                a1 = fma2(wp[k], rv.y, a1);
            }
            F2U u0, u1; u0.u = a0; u1.u = a1;
            *(float4*)&wout[p4] = make_float4(u0.f.x, u0.f.y, u1.f.x, u1.f.y);
        }
    }
}

// =====================================================================
// K3: involution (R3-measured version: plain fmaf, static smem, occ 2).
// =====================================================================
__global__ __launch_bounds__(256, 2)
void k3_involution(float* __restrict__ outp) {
    __shared__ float Hs[16 * 336];
    __shared__ float Wg[KK * 256];

    const int tile = blockIdx.x;
    const int g    = blockIdx.y;
    const int bb   = blockIdx.z;
    const int m0   = (tile >> 2) * 16;
    const int n0   = (tile & 3) * 16;
    const int t    = threadIdx.x;

    for (int idx = t; idx < 16 * 324; idx += 256) {
        int c  = idx / 324;
        int r2 = idx - c * 324;
        int mm = r2 / 18;
        int nn = r2 - mm * 18;
        int gm = m0 + mm - 1;
        int gn = n0 + nn - 1;
        float v = 0.f;
        if (gm >= 0 && gm < HLO && gn >= 0 && gn < WLO)
            v = g_h0[((size_t)(bb * COUT + g * GC_ + c)) * PLO + gm * WLO + gn];
        Hs[c * 336 + mm * 18 + nn] = v;
    }
    for (int idx = t; idx < KK * 256; idx += 256) {
        int k  = idx >> 8;
        int pp = idx & 255;
        int ml = pp >> 4;
        int nl = pp & 15;
        Wg[idx] = g_wgt[((size_t)(bb * SPAN + g * KK + k)) * PLO + (m0 + ml) * WLO + (n0 + nl)];
    }
    __syncthreads();

    const int c  = t >> 4;
    const int nl = t & 15;
    const int xg = (n0 + nl) * 2;

    for (int ml = 0; ml < 16; ml++) {
        float wv[KK];
#pragma unroll
        for (int k = 0; k < KK; k++) wv[k] = Wg[k * 256 + ml * 16 + nl];
        float hv[9];
#pragma unroll
        for (int dr = 0; dr < 3; dr++)
#pragma unroll
            for (int dc = 0; dc < 3; dc++)
                hv[dr * 3 + dc] = Hs[c * 336 + (ml + dr) * 18 + (nl + dc)];

        float a00 = 0.f, a01 = 0.f, a10 = 0.f, a11 = 0.f;
#pragma unroll
        for (int kh = 0; kh < 5; kh++) {
#pragma unroll
            for (int kw = 0; kw < 5; kw++) {
                const float w = wv[kh * 5 + kw];
                const int r0 = ((kh - 2) >> 1) + 1;
                const int r1 = ((kh - 1) >> 1) + 1;
                const int c0 = ((kw - 2) >> 1) + 1;
                const int c1 = ((kw - 1) >> 1) + 1;
                a00 = fmaf(w, hv[r0 * 3 + c0], a00);
                a01 = fmaf(w, hv[r0 * 3 + c1], a01);
                a10 = fmaf(w, hv[r1 * 3 + c0], a10);
                a11 = fmaf(w, hv[r1 * 3 + c1], a11);
            }
        }
        const int yb = (m0 + ml) * 2;
        size_t ob = ((size_t)(bb * COUT + g * GC_ + c) * HF + yb) * WF + xg;
        *(float2*)&outp[ob]      = make_float2(a00, a01);
        *(float2*)&outp[ob + WF] = make_float2(a10, a11);
    }
}

// =====================================================================
extern "C" void kernel_launch(void* const* d_in, const int* in_sizes, int n_in,
                              void* d_out, int out_size) {
    const float* x      = (const float*)d_in[0];
    const float* w1x1   = (const float*)d_in[1];
    const float* b1x1   = (const float*)d_in[2];
    const float* w_red  = (const float*)d_in[3];
    const float* b_red  = (const float*)d_in[4];
    const float* gamma  = (const float*)d_in[5];
    const float* beta   = (const float*)d_in[6];
    const float* mean   = (const float*)d_in[7];
    const float* var    = (const float*)d_in[8];
    const float* w_span = (const float*)d_in[9];
    const float* b_span = (const float*)d_in[10];
    float* out = (float*)d_out;

    k1_conv1x1 <<<dim3(PLO / 128, 2, B_), 128>>>(x, w1x1, b1x1);
    k2_kernelgen<<<dim3(PLO / 128, B_), 256>>>(w_red, b_red, gamma, beta, mean, var,
                                               w_span, b_span);
    k3_involution<<<dim3(16, GROUPS, B_), 256>>>(out);
}